// round 14
// baseline (speedup 1.0000x reference)
#include <cuda_runtime.h>
#include <cstdint>

// TVConv: per-pixel spatially-varying 3x3 depthwise conv.
// x:           (B=8, C=96, H=128, W=128) f32
// weight_maps: (1, C=96, 3, 3, H=128, W=128) f32
// out:         (B=8, C=96, H=128, W=128) f32
//
// CTA = (channel c, 8-row strip), 256 threads. All 8 batch x-tiles resident
// in smem (43.5 KB). Staging now uses cp.async.bulk (TMA/bulk pipe, idle
// until now) instead of 2560 per-thread LDGSTS: thread 0 issues 10 row
// copies of 512 B per tile with mbarrier complete_tx (one mbarrier per
// buffer), so the L1tex queue never sees staging traffic and the front-
// batched-LDG cross-CTA spread penalty disappears. Weights (36/thread) load
// once via LDG, overlapping tile arrival. Compute phases gate on per-buffer
// mbarrier parity waits (acquire) -> single __syncthreads in the whole
// kernel. Halo cols + out-of-range halo rows pre-zeroed (disjoint from bulk
// writes).

#define BB 8
#define CC 96
#define HH 128
#define WW 128
#define TH 8          // output rows per block
#define RPT 4         // rows per thread
#define SPITCH 136    // floats per shared row (interior [4..131], halos [3],[132])
#define TROWS (TH + 2)

__device__ __forceinline__ uint32_t smem_u32(const void* p) {
    return (uint32_t)__cvta_generic_to_shared(p);
}

__device__ __forceinline__ void mbar_init(uint32_t mbar, uint32_t count) {
    asm volatile("mbarrier.init.shared.b64 [%0], %1;" :: "r"(mbar), "r"(count) : "memory");
}
__device__ __forceinline__ void mbar_expect_tx(uint32_t mbar, uint32_t bytes) {
    asm volatile("mbarrier.arrive.expect_tx.shared.b64 _, [%0], %1;"
                 :: "r"(mbar), "r"(bytes) : "memory");
}
__device__ __forceinline__ void mbar_wait(uint32_t mbar, uint32_t parity) {
    asm volatile(
        "{\n\t"
        ".reg .pred P1;\n\t"
        "WAIT_LOOP_%=:\n\t"
        "mbarrier.try_wait.parity.acquire.cta.shared::cta.b64 P1, [%0], %1, 0x989680;\n\t"
        "@P1 bra.uni WAIT_DONE_%=;\n\t"
        "bra.uni WAIT_LOOP_%=;\n\t"
        "WAIT_DONE_%=:\n\t"
        "}"
        :: "r"(mbar), "r"(parity) : "memory");
}
__device__ __forceinline__ void bulk_copy(uint32_t smem_dst, const void* gsrc,
                                          uint32_t bytes, uint32_t mbar) {
    asm volatile(
        "cp.async.bulk.shared::cta.global.mbarrier::complete_tx::bytes [%0], [%1], %2, [%3];"
        :: "r"(smem_dst), "l"(gsrc), "r"(bytes), "r"(mbar) : "memory");
}

__global__ __launch_bounds__(256, 4)
void tvconv_kernel(const float* __restrict__ x,
                   const float* __restrict__ wm,
                   float* __restrict__ out) {
    const int c   = blockIdx.y;
    const int h0  = blockIdx.x * TH;
    const int tid = threadIdx.x;
    const int tw  = tid & (WW - 1);   // 0..127 -> output w
    const int ty  = tid >> 7;         // 0..1

    __shared__ __align__(16) float sx[BB][TROWS * SPITCH];   // 43,520 B
    __shared__ __align__(8)  uint64_t mbar[BB];

    const int plane  = HH * WW;       // 16384
    const int cplane = c * plane;
    const float* wmc = wm + c * 9 * plane;

    // ---- init per-buffer mbarriers ----
    if (tid == 0) {
        #pragma unroll
        for (int b = 0; b < BB; b++) mbar_init(smem_u32(&mbar[b]), 1);
    }

    // ---- pre-zero: halo cols (all bufs) + out-of-range halo row interiors ----
    // halo cols: 8 bufs x 10 rows x 2 = 160 writes
    if (tid < BB * TROWS * 2) {
        int buf  = tid / (TROWS * 2);
        int rem  = tid - buf * (TROWS * 2);
        int r    = rem >> 1;
        int side = rem & 1;
        sx[buf][r * SPITCH + (side ? 132 : 3)] = 0.0f;
    }
    const bool top = (h0 == 0);
    const bool bot = (h0 + TH == HH);
    if (top | bot) {
        const int zrow = top ? 0 : (TROWS - 1);
        // 8 bufs x 128 interior floats = 1024 writes
        for (int i = tid; i < BB * WW; i += 256) {
            int buf = i >> 7;
            int col = i & (WW - 1);
            sx[buf][zrow * SPITCH + 4 + col] = 0.0f;
        }
    }
    __syncthreads();   // mbarrier init + zeros visible before issue/compute

    // ---- thread 0 issues all bulk copies (row granularity, 512 B each) ----
    if (tid == 0) {
        const int r_lo = top ? 1 : 0;
        const int r_hi = bot ? (TROWS - 1) : TROWS;   // exclusive
        const uint32_t bytes = (uint32_t)(r_hi - r_lo) * WW * 4;
        #pragma unroll
        for (int b = 0; b < BB; b++) {
            const float* xb = x + (b * CC) * plane + cplane;
            const uint32_t mb = smem_u32(&mbar[b]);
            mbar_expect_tx(mb, bytes);
            for (int r = r_lo; r < r_hi; r++) {
                const int gh = h0 - 1 + r;
                bulk_copy(smem_u32(&sx[b][r * SPITCH + 4]),
                          xb + gh * WW, WW * 4, mb);
            }
        }
    }

    // ---- load 4x9 weights into registers (overlaps tile arrival) ----
    float wreg[RPT][9];
    #pragma unroll
    for (int r = 0; r < RPT; r++) {
        const int h = h0 + ty + 2 * r;
        const int base = h * WW + tw;
        #pragma unroll
        for (int t = 0; t < 9; t++) {
            wreg[r][t] = __ldg(&wmc[t * plane + base]);
        }
    }

    // ---- consume: per-buffer mbarrier wait (acquire), no further barriers ----
    #define COMPUTE_BATCH(B)                                                  \
    {                                                                         \
        mbar_wait(smem_u32(&mbar[(B)]), 0);                                   \
        float* ob = out + ((B) * CC) * plane + cplane;                        \
        _Pragma("unroll")                                                     \
        for (int r = 0; r < RPT; r++) {                                       \
            const int lr = ty + 2 * r;                                        \
            float acc = 0.0f;                                                 \
            _Pragma("unroll")                                                 \
            for (int kh = 0; kh < 3; kh++) {                                  \
                const float* sr = &sx[(B)][(lr + kh) * SPITCH + tw + 3];      \
                acc = fmaf(wreg[r][kh * 3 + 0], sr[0], acc);                  \
                acc = fmaf(wreg[r][kh * 3 + 1], sr[1], acc);                  \
                acc = fmaf(wreg[r][kh * 3 + 2], sr[2], acc);                  \
            }                                                                 \
            ob[(h0 + lr) * WW + tw] = acc;                                    \
        }                                                                     \
    }

    COMPUTE_BATCH(0) COMPUTE_BATCH(1) COMPUTE_BATCH(2) COMPUTE_BATCH(3)
    COMPUTE_BATCH(4) COMPUTE_BATCH(5) COMPUTE_BATCH(6) COMPUTE_BATCH(7)

    #undef COMPUTE_BATCH
}

extern "C" void kernel_launch(void* const* d_in, const int* in_sizes, int n_in,
                              void* d_out, int out_size) {
    const float* x  = (const float*)d_in[0];
    const float* wm = (const float*)d_in[1];
    float* out = (float*)d_out;

    dim3 grid(HH / TH, CC);   // 16 x 96 = 1536 CTAs
    tvconv_kernel<<<grid, 256>>>(x, wm, out);
}